// round 4
// baseline (speedup 1.0000x reference)
#include <cuda_runtime.h>
#include <cstdint>
#include <cstdio>

// Problem-size capacities (from reference setup: N=20000, E=320000)
#define NMAXN 20000
#define EMAXE 320000
#define ETOT  (NMAXN + EMAXE)

// ---------------- static device scratch (no allocations allowed) ----------------
__device__ __align__(16) float g_xl1[NMAXN * 256];
__device__ __align__(16) float g_xr1[NMAXN * 256];
__device__ __align__(16) float g_h1 [NMAXN * 256];
__device__ __align__(16) float g_xl2[NMAXN * 64];
__device__ __align__(16) float g_xr2[NMAXN * 64];
__device__ __align__(16) float g_h2 [NMAXN * 64];
__device__ int   g_deg[NMAXN + 1];
__device__ int   g_off[NMAXN + 1];
__device__ int   g_cur[NMAXN];
__device__ int   g_csrc[ETOT];
__device__ float g_sum[64];
__device__ float g_sumsq[64];

// ---------------- init: deg=1 accounts for the self-loop ----------------
__global__ void k_init(int N) {
    int i = blockIdx.x * blockDim.x + threadIdx.x;
    if (i < N) g_deg[i] = 1;
    if (i < 64) { g_sum[i] = 0.f; g_sumsq[i] = 0.f; }
}

// ---------------- CSR build (by dst), E edges only ----------------
__global__ void k_count(const int* __restrict__ ei, int E) {
    int i = blockIdx.x * blockDim.x + threadIdx.x;
    if (i >= E) return;
    atomicAdd(&g_deg[__ldg(ei + E + i)], 1);
}

// single-block chunked scan; also writes the self-loop into slot 0 of each
// node's segment and initializes g_cur = off + 1.
#define SCAN_PER ((NMAXN + 1023) / 1024)
__global__ __launch_bounds__(1024) void k_scan2(int N) {
    __shared__ int sh[1024];
    int tid = threadIdx.x;
    int base = tid * SCAN_PER;
    int vals[SCAN_PER];
    int s = 0;
    #pragma unroll
    for (int i = 0; i < SCAN_PER; i++) {
        int idx = base + i;
        int v = (idx < N) ? g_deg[idx] : 0;
        vals[i] = s;          // exclusive within chunk
        s += v;
    }
    sh[tid] = s;
    __syncthreads();
    #pragma unroll
    for (int o = 1; o < 1024; o <<= 1) {
        int t = (tid >= o) ? sh[tid - o] : 0;
        __syncthreads();
        sh[tid] += t;
        __syncthreads();
    }
    int block_excl = sh[tid] - s;
    #pragma unroll
    for (int i = 0; i < SCAN_PER; i++) {
        int idx = base + i;
        if (idx < N) {
            int o = block_excl + vals[i];
            g_off[idx] = o;
            g_csrc[o] = idx;      // self-loop occupies slot 0
            g_cur[idx] = o + 1;
        }
    }
    if (tid == 1023) g_off[N] = sh[1023];
}

__global__ void k_fill(const int* __restrict__ ei, int E) {
    int i = blockIdx.x * blockDim.x + threadIdx.x;
    if (i >= E) return;
    int src = __ldg(ei + i);
    int dst = __ldg(ei + E + i);
    int pos = atomicAdd(&g_cur[dst], 1);
    g_csrc[pos] = src;
}

// ---------------- tf32 tensor-core GEMM ----------------
// C_concat[M, 2H] = A[M, K] @ concat(B0, B1)[K, 2H], written to C0/C1 halves.
// Block: 256 threads = 8 warps (2 m x 4 n), tile 64(M) x 128(N) x 32(K).
__device__ __forceinline__ unsigned f2tf32(float f) {
    unsigned u;
    asm("cvt.rna.tf32.f32 %0, %1;" : "=r"(u) : "f"(f));
    return u;
}

__device__ __forceinline__ void mma_tf32(float* d, const unsigned* a, unsigned b0, unsigned b1) {
    asm volatile(
        "mma.sync.aligned.m16n8k8.row.col.f32.tf32.tf32.f32 "
        "{%0,%1,%2,%3}, {%4,%5,%6,%7}, {%8,%9}, {%0,%1,%2,%3};"
        : "+f"(d[0]), "+f"(d[1]), "+f"(d[2]), "+f"(d[3])
        : "r"(a[0]), "r"(a[1]), "r"(a[2]), "r"(a[3]), "r"(b0), "r"(b1));
}

__global__ __launch_bounds__(256) void k_mma(
    const float* __restrict__ A,
    const float* __restrict__ B0, const float* __restrict__ B1,
    float* __restrict__ C0, float* __restrict__ C1,
    int M, int K, int H)
{
    __shared__ float As[64][36];    // [m][k], pad 36 -> conflict-free frag loads
    __shared__ float Bs[32][136];   // [k][n], pad 136 -> conflict-free frag loads

    int tid = threadIdx.x;
    int lane = tid & 31, warp = tid >> 5;
    int wm = warp & 1, wn = warp >> 1;     // 2 x 4 warp grid
    int m0 = blockIdx.x * 64;
    int n0g = blockIdx.y * 128;            // col in concatenated [0, 2H) space
    int g = lane >> 2, tg = lane & 3;

    float acc[2][4][4];
    #pragma unroll
    for (int mt = 0; mt < 2; mt++)
        #pragma unroll
        for (int nt = 0; nt < 4; nt++)
            #pragma unroll
            for (int i = 0; i < 4; i++) acc[mt][nt][i] = 0.f;

    int ar = tid >> 2;          // 0..63
    int ac = (tid & 3) * 8;     // 0,8,16,24
    int br = tid >> 3;          // 0..31
    int bc = (tid & 7) * 16;    // 0..112

    for (int k0 = 0; k0 < K; k0 += 32) {
        // A tile 64x32
        float4 v0 = make_float4(0.f, 0.f, 0.f, 0.f), v1 = v0;
        if (m0 + ar < M) {
            const float* ap = A + (size_t)(m0 + ar) * K + k0 + ac;
            v0 = *reinterpret_cast<const float4*>(ap);
            v1 = *reinterpret_cast<const float4*>(ap + 4);
        }
        As[ar][ac + 0] = __uint_as_float(f2tf32(v0.x));
        As[ar][ac + 1] = __uint_as_float(f2tf32(v0.y));
        As[ar][ac + 2] = __uint_as_float(f2tf32(v0.z));
        As[ar][ac + 3] = __uint_as_float(f2tf32(v0.w));
        As[ar][ac + 4] = __uint_as_float(f2tf32(v1.x));
        As[ar][ac + 5] = __uint_as_float(f2tf32(v1.y));
        As[ar][ac + 6] = __uint_as_float(f2tf32(v1.z));
        As[ar][ac + 7] = __uint_as_float(f2tf32(v1.w));

        // B tile 32x128 (columns may span the B0/B1 halves; halves are 64-multiples)
        #pragma unroll
        for (int i = 0; i < 4; i++) {
            int col = n0g + bc + i * 4;
            const float* bp = (col < H)
                ? B0 + (size_t)(k0 + br) * H + col
                : B1 + (size_t)(k0 + br) * H + (col - H);
            float4 b = *reinterpret_cast<const float4*>(bp);
            Bs[br][bc + i * 4 + 0] = __uint_as_float(f2tf32(b.x));
            Bs[br][bc + i * 4 + 1] = __uint_as_float(f2tf32(b.y));
            Bs[br][bc + i * 4 + 2] = __uint_as_float(f2tf32(b.z));
            Bs[br][bc + i * 4 + 3] = __uint_as_float(f2tf32(b.w));
        }
        __syncthreads();

        #pragma unroll
        for (int kk = 0; kk < 32; kk += 8) {
            unsigned afr[2][4];
            #pragma unroll
            for (int mt = 0; mt < 2; mt++) {
                int row = wm * 32 + mt * 16;
                afr[mt][0] = __float_as_uint(As[row + g    ][kk + tg    ]);
                afr[mt][1] = __float_as_uint(As[row + g + 8][kk + tg    ]);
                afr[mt][2] = __float_as_uint(As[row + g    ][kk + tg + 4]);
                afr[mt][3] = __float_as_uint(As[row + g + 8][kk + tg + 4]);
            }
            #pragma unroll
            for (int nt = 0; nt < 4; nt++) {
                int ncol = wn * 32 + nt * 8;
                unsigned b0 = __float_as_uint(Bs[kk + tg    ][ncol + g]);
                unsigned b1 = __float_as_uint(Bs[kk + tg + 4][ncol + g]);
                #pragma unroll
                for (int mt = 0; mt < 2; mt++)
                    mma_tf32(acc[mt][nt], afr[mt], b0, b1);
            }
        }
        __syncthreads();
    }

    // store: c0,c1 -> (row, 2tg..2tg+1); c2,c3 -> (row+8, ...)
    #pragma unroll
    for (int mt = 0; mt < 2; mt++) {
        int r0 = m0 + wm * 32 + mt * 16 + g;
        #pragma unroll
        for (int nt = 0; nt < 4; nt++) {
            int col = n0g + wn * 32 + nt * 8 + tg * 2;
            float* Cp = C0;
            int c = col;
            if (col >= H) { Cp = C1; c = col - H; }
            if (r0 < M)
                *reinterpret_cast<float2*>(Cp + (size_t)r0 * H + c) =
                    make_float2(acc[mt][nt][0], acc[mt][nt][1]);
            if (r0 + 8 < M)
                *reinterpret_cast<float2*>(Cp + (size_t)(r0 + 8) * H + c) =
                    make_float2(acc[mt][nt][2], acc[mt][nt][3]);
        }
    }
}

// ---------------- vector load helper ----------------
template <int V>
__device__ __forceinline__ void loadv(float* d, const float* __restrict__ p) {
    if constexpr (V == 8) {
        float4 a = *reinterpret_cast<const float4*>(p);
        float4 b = *reinterpret_cast<const float4*>(p + 4);
        d[0] = a.x; d[1] = a.y; d[2] = a.z; d[3] = a.w;
        d[4] = b.x; d[5] = b.y; d[6] = b.z; d[7] = b.w;
    } else if constexpr (V == 2) {
        float2 a = *reinterpret_cast<const float2*>(p);
        d[0] = a.x; d[1] = a.y;
    } else {
        #pragma unroll
        for (int j = 0; j < V; j++) d[j] = p[j];
    }
}

// ---------------- GATv2 node aggregation: warp per node, online softmax ----------------
// HC = H*C total width; VPT = HC/32 per lane; REDW = 32/H lanes per head.
// Branch-free online softmax + 1-deep software prefetch of xl rows.
// STATS: fuse per-channel sum/sumsq accumulation (layer-2 InstanceNorm).
template <int HC, int VPT, int REDW, bool ELU_ACT, bool STATS>
__global__ __launch_bounds__(256) void k_node_agg(
    const float* __restrict__ xl, const float* __restrict__ xr,
    const float* __restrict__ att, const float* __restrict__ bias,
    float* __restrict__ outp, int N)
{
    __shared__ float sh_sum[STATS ? 64 : 1];
    __shared__ float sh_sq [STATS ? 64 : 1];
    int tid = threadIdx.x;
    if (STATS) {
        if (tid < 64) { sh_sum[tid] = 0.f; sh_sq[tid] = 0.f; }
        __syncthreads();
    }

    int warp = (blockIdx.x * blockDim.x + tid) >> 5;
    int lane = tid & 31;
    bool active = warp < N;
    int c0 = lane * VPT;

    if (active) {
        int n = warp;
        float xrv[VPT], attv[VPT], acc[VPT];
        loadv<VPT>(xrv, xr + (size_t)n * HC + c0);
        loadv<VPT>(attv, att + c0);
        #pragma unroll
        for (int j = 0; j < VPT; j++) acc[j] = 0.f;

        float m = __int_as_float(0xff800000);   // -inf
        float denom = 0.f;

        int s = g_off[n], e = g_off[n + 1];
        // prefetch first row (every node has >= 1 edge: the self-loop)
        float nxt[VPT];
        loadv<VPT>(nxt, xl + (size_t)g_csrc[s] * HC + c0);

        for (int i = s; i < e; i++) {
            float xlv[VPT];
            #pragma unroll
            for (int j = 0; j < VPT; j++) xlv[j] = nxt[j];
            if (i + 1 < e)
                loadv<VPT>(nxt, xl + (size_t)g_csrc[i + 1] * HC + c0);

            float sc = 0.f;
            #pragma unroll
            for (int j = 0; j < VPT; j++) {
                float t = xlv[j] + xrv[j];
                t = (t > 0.f) ? t : 0.2f * t;   // leaky_relu slope 0.2
                sc = fmaf(t, attv[j], sc);
            }
            #pragma unroll
            for (int w = 1; w < REDW; w <<= 1)
                sc += __shfl_xor_sync(0xffffffffu, sc, w);

            // branch-free online softmax update
            float newm = fmaxf(m, sc);
            float r  = __expf(m - newm);        // 0 on first edge (m = -inf)
            float ex = __expf(sc - newm);
            denom = fmaf(denom, r, ex);
            #pragma unroll
            for (int j = 0; j < VPT; j++)
                acc[j] = fmaf(acc[j], r, ex * xlv[j]);
            m = newm;
        }

        float inv = 1.f / (denom + 1e-16f);
        #pragma unroll
        for (int j = 0; j < VPT; j++) {
            float v = acc[j] * inv + bias[c0 + j];
            if (ELU_ACT) v = (v > 0.f) ? v : (__expf(v) - 1.f);  // ELU alpha=1
            outp[(size_t)n * HC + c0 + j] = v;
            if (STATS) {
                atomicAdd(&sh_sum[c0 + j], v);
                atomicAdd(&sh_sq [c0 + j], v * v);
            }
        }
    }

    if (STATS) {
        __syncthreads();
        if (tid < 64) {
            atomicAdd(&g_sum[tid],   sh_sum[tid]);
            atomicAdd(&g_sumsq[tid], sh_sq[tid]);
        }
    }
}

// ---------------- InstanceNorm + log_softmax epilogue (warp per node) ----------------
__global__ __launch_bounds__(256) void k_final(
    const float* __restrict__ h,
    const float* __restrict__ gamma, const float* __restrict__ beta,
    float* __restrict__ out, int N)
{
    int gw = (blockIdx.x * blockDim.x + threadIdx.x) >> 5;
    int lane = threadIdx.x & 31;
    if (gw >= N) return;
    int c0 = lane * 2;

    float2 x = *reinterpret_cast<const float2*>(h + (size_t)gw * 64 + c0);
    float invN = 1.f / (float)N;

    float mean0 = g_sum[c0] * invN;
    float var0  = g_sumsq[c0] * invN - mean0 * mean0;
    float y0 = (x.x - mean0) * rsqrtf(var0 + 1e-5f) * gamma[c0] + beta[c0];

    float mean1 = g_sum[c0 + 1] * invN;
    float var1  = g_sumsq[c0 + 1] * invN - mean1 * mean1;
    float y1 = (x.y - mean1) * rsqrtf(var1 + 1e-5f) * gamma[c0 + 1] + beta[c0 + 1];

    float2 yv = make_float2(y0, y1);
    *reinterpret_cast<float2*>(out + (size_t)gw * 64 + c0) = yv;

    float mx = fmaxf(y0, y1);
    #pragma unroll
    for (int w = 1; w < 32; w <<= 1) mx = fmaxf(mx, __shfl_xor_sync(0xffffffffu, mx, w));
    float se = __expf(y0 - mx) + __expf(y1 - mx);
    #pragma unroll
    for (int w = 1; w < 32; w <<= 1) se += __shfl_xor_sync(0xffffffffu, se, w);
    float ls = __logf(se) + mx;          // log-sum-exp

    float2 lv = make_float2(y0 - ls, y1 - ls);
    *reinterpret_cast<float2*>(out + (size_t)N * 64 + (size_t)gw * 64 + c0) = lv;
}

// ---------------- host launcher ----------------
extern "C" void kernel_launch(void* const* d_in, const int* in_sizes, int n_in,
                              void* d_out, int out_size)
{
    const float* x     = (const float*)d_in[0];
    const float* Wl1   = (const float*)d_in[1];
    const float* Wr1   = (const float*)d_in[2];
    const float* att1  = (const float*)d_in[3];
    const float* b1    = (const float*)d_in[4];
    const float* Wl2   = (const float*)d_in[5];
    const float* Wr2   = (const float*)d_in[6];
    const float* att2  = (const float*)d_in[7];
    const float* b2    = (const float*)d_in[8];
    const float* gamma = (const float*)d_in[9];
    const float* beta  = (const float*)d_in[10];
    const int*   ei    = (const int*)  d_in[11];   // [2, E] int32

    int N = in_sizes[0] / 128;
    int E = in_sizes[11] / 2;

    void *p;
    cudaGetSymbolAddress(&p, g_xl1); float* xl1 = (float*)p;
    cudaGetSymbolAddress(&p, g_xr1); float* xr1 = (float*)p;
    cudaGetSymbolAddress(&p, g_h1 ); float* h1  = (float*)p;
    cudaGetSymbolAddress(&p, g_xl2); float* xl2 = (float*)p;
    cudaGetSymbolAddress(&p, g_xr2); float* xr2 = (float*)p;
    cudaGetSymbolAddress(&p, g_h2 ); float* h2  = (float*)p;

    // CSR build (self-loops folded into init/scan)
    k_init<<<(N + 255) / 256, 256>>>(N);
    k_count<<<(E + 255) / 256, 256>>>(ei, E);
    k_scan2<<<1, 1024>>>(N);
    k_fill<<<(E + 255) / 256, 256>>>(ei, E);

    // Layer 1: [xl1 | xr1] = x @ [Wl1 | Wr1]  (M=N, K=128, H=256, 2H=512)
    {
        dim3 grid((N + 63) / 64, 4);
        k_mma<<<grid, 256>>>(x, Wl1, Wr1, xl1, xr1, N, 128, 256);
    }
    // GATv2 layer 1 (H=8, C=32) + bias + ELU
    k_node_agg<256, 8, 4, true, false><<<(N * 32 + 255) / 256, 256>>>(xl1, xr1, att1, b1, h1, N);

    // Layer 2: [xl2 | xr2] = h1 @ [Wl2 | Wr2]  (M=N, K=256, H=64, 2H=128)
    {
        dim3 grid((N + 63) / 64, 1);
        k_mma<<<grid, 256>>>(h1, Wl2, Wr2, xl2, xr2, N, 256, 64);
    }
    // GATv2 layer 2 (H=1, C=64) + bias + fused InstanceNorm stats
    k_node_agg<64, 2, 32, false, true><<<(N * 32 + 255) / 256, 256>>>(xl2, xr2, att2, b2, h2, N);

    // InstanceNorm normalize + log_softmax
    k_final<<<(N * 32 + 255) / 256, 256>>>(h2, gamma, beta, (float*)d_out, N);
}

// round 5
// speedup vs baseline: 1.0097x; 1.0097x over previous
#include <cuda_runtime.h>
#include <cstdint>
#include <cstdio>

// Problem-size capacities (from reference setup: N=20000, E=320000)
#define NMAXN 20000
#define EMAXE 320000
#define ETOT  (NMAXN + EMAXE)

// ---------------- static device scratch (no allocations allowed) ----------------
__device__ __align__(16) float g_xl1[NMAXN * 256];
__device__ __align__(16) float g_xr1[NMAXN * 256];
__device__ __align__(16) float g_h1 [NMAXN * 256];
__device__ __align__(16) float g_xl2[NMAXN * 64];
__device__ __align__(16) float g_xr2[NMAXN * 64];
__device__ __align__(16) float g_h2 [NMAXN * 64];
__device__ int   g_deg[NMAXN + 1];
__device__ int   g_off[NMAXN + 1];
__device__ int   g_cur[NMAXN];
__device__ int   g_csrc[ETOT];
__device__ float g_sum[64];
__device__ float g_sumsq[64];

// ---------------- init: deg=1 accounts for the self-loop ----------------
__global__ void k_init(int N) {
    int i = blockIdx.x * blockDim.x + threadIdx.x;
    if (i < N) g_deg[i] = 1;
    if (i < 64) { g_sum[i] = 0.f; g_sumsq[i] = 0.f; }
}

// ---------------- CSR build (by dst), E edges only ----------------
__global__ void k_count(const int* __restrict__ ei, int E) {
    int i = blockIdx.x * blockDim.x + threadIdx.x;
    if (i >= E) return;
    atomicAdd(&g_deg[__ldg(ei + E + i)], 1);
}

// single-block chunked scan; writes the self-loop into slot 0 of each
// node's segment and initializes g_cur = off + 1.
#define SCAN_PER ((NMAXN + 1023) / 1024)
__global__ __launch_bounds__(1024) void k_scan2(int N) {
    __shared__ int sh[1024];
    int tid = threadIdx.x;
    int base = tid * SCAN_PER;
    int vals[SCAN_PER];
    int s = 0;
    #pragma unroll
    for (int i = 0; i < SCAN_PER; i++) {
        int idx = base + i;
        int v = (idx < N) ? g_deg[idx] : 0;
        vals[i] = s;          // exclusive within chunk
        s += v;
    }
    sh[tid] = s;
    __syncthreads();
    #pragma unroll
    for (int o = 1; o < 1024; o <<= 1) {
        int t = (tid >= o) ? sh[tid - o] : 0;
        __syncthreads();
        sh[tid] += t;
        __syncthreads();
    }
    int block_excl = sh[tid] - s;
    #pragma unroll
    for (int i = 0; i < SCAN_PER; i++) {
        int idx = base + i;
        if (idx < N) {
            int o = block_excl + vals[i];
            g_off[idx] = o;
            g_csrc[o] = idx;      // self-loop occupies slot 0
            g_cur[idx] = o + 1;
        }
    }
    if (tid == 1023) g_off[N] = sh[1023];
}

__global__ void k_fill(const int* __restrict__ ei, int E) {
    int i = blockIdx.x * blockDim.x + threadIdx.x;
    if (i >= E) return;
    int src = __ldg(ei + i);
    int dst = __ldg(ei + E + i);
    int pos = atomicAdd(&g_cur[dst], 1);
    g_csrc[pos] = src;
}

// ---------------- tf32 tensor-core GEMM, cp.async double-buffered ----------------
// C_concat[M, 2H] = A[M, K] @ concat(B0, B1)[K, 2H], written to C0/C1 halves.
// Block: 256 threads = 8 warps (2 m x 4 n), tile 64(M) x 128(N) x 32(K).
__device__ __forceinline__ unsigned f2tf32(float f) {
    unsigned u;
    asm("cvt.rna.tf32.f32 %0, %1;" : "=r"(u) : "f"(f));
    return u;
}

__device__ __forceinline__ void mma_tf32(float* d, const unsigned* a, unsigned b0, unsigned b1) {
    asm volatile(
        "mma.sync.aligned.m16n8k8.row.col.f32.tf32.tf32.f32 "
        "{%0,%1,%2,%3}, {%4,%5,%6,%7}, {%8,%9}, {%0,%1,%2,%3};"
        : "+f"(d[0]), "+f"(d[1]), "+f"(d[2]), "+f"(d[3])
        : "r"(a[0]), "r"(a[1]), "r"(a[2]), "r"(a[3]), "r"(b0), "r"(b1));
}

__device__ __forceinline__ void cp_async16(uint32_t saddr, const void* g, int srcbytes) {
    asm volatile("cp.async.cg.shared.global [%0], [%1], 16, %2;"
                 :: "r"(saddr), "l"(g), "r"(srcbytes));
}

#define AS_STRIDE 36
#define BS_STRIDE 136
#define AS_STAGE  (64 * AS_STRIDE)      // floats per A stage
#define BS_STAGE  (32 * BS_STRIDE)      // floats per B stage
#define SMEM_MMA_BYTES ((2 * AS_STAGE + 2 * BS_STAGE) * 4)

__global__ __launch_bounds__(256) void k_mma(
    const float* __restrict__ A,
    const float* __restrict__ B0, const float* __restrict__ B1,
    float* __restrict__ C0, float* __restrict__ C1,
    int M, int K, int H)
{
    extern __shared__ float smem[];
    float* sAs = smem;                       // [2][64][36]
    float* sBs = smem + 2 * AS_STAGE;        // [2][32][136]

    int tid = threadIdx.x;
    int lane = tid & 31, warp = tid >> 5;
    int wm = warp & 1, wn = warp >> 1;       // 2 x 4 warp grid
    int m0 = blockIdx.x * 64;
    int n0g = blockIdx.y * 128;              // col in concatenated [0, 2H) space
    int g = lane >> 2, tg = lane & 3;

    float acc[2][4][4];
    #pragma unroll
    for (int mt = 0; mt < 2; mt++)
        #pragma unroll
        for (int nt = 0; nt < 4; nt++)
            #pragma unroll
            for (int i = 0; i < 4; i++) acc[mt][nt][i] = 0.f;

    int ar = tid >> 2;          // 0..63
    int ac = (tid & 3) * 8;     // 0,8,16,24
    int br = tid >> 3;          // 0..31
    int bc = (tid & 7) * 16;    // 0..112

    // per-thread source pointers / predicates (row clamped, zero-filled when OOB)
    int arow = m0 + ar;
    int apred = (arow < M) ? 16 : 0;
    if (arow >= M) arow = M - 1;
    const float* abase = A + (size_t)arow * K + ac;

    const float* bsrc[4];
    #pragma unroll
    for (int i = 0; i < 4; i++) {
        int col = n0g + bc + i * 4;
        bsrc[i] = (col < H) ? (B0 + (size_t)br * H + col)
                            : (B1 + (size_t)br * H + (col - H));
    }

    uint32_t sA0 = (uint32_t)__cvta_generic_to_shared(sAs);
    uint32_t sB0 = (uint32_t)__cvta_generic_to_shared(sBs);

    int nIter = K >> 5;

    // ---- stage loader ----
    auto load_stage = [&](int k0, int st) {
        uint32_t sa = sA0 + (st * AS_STAGE + ar * AS_STRIDE + ac) * 4;
        const float* ap = abase + k0;
        cp_async16(sa,      ap,     apred);
        cp_async16(sa + 16, ap + 4, apred);
        uint32_t sb = sB0 + (st * BS_STAGE + br * BS_STRIDE + bc) * 4;
        size_t koff = (size_t)k0 * H;
        #pragma unroll
        for (int i = 0; i < 4; i++)
            cp_async16(sb + i * 16, bsrc[i] + koff, 16);
    };

    load_stage(0, 0);
    asm volatile("cp.async.commit_group;" ::: "memory");

    for (int it = 0; it < nIter; it++) {
        int st = it & 1;
        asm volatile("cp.async.wait_group 0;" ::: "memory");
        __syncthreads();
        if (it + 1 < nIter) {
            load_stage((it + 1) << 5, st ^ 1);
            asm volatile("cp.async.commit_group;" ::: "memory");
        }

        const float* As = sAs + st * AS_STAGE;
        const float* Bs = sBs + st * BS_STAGE;

        #pragma unroll
        for (int kk = 0; kk < 32; kk += 8) {
            unsigned afr[2][4];
            #pragma unroll
            for (int mt = 0; mt < 2; mt++) {
                int row = wm * 32 + mt * 16;
                afr[mt][0] = f2tf32(As[(row + g    ) * AS_STRIDE + kk + tg    ]);
                afr[mt][1] = f2tf32(As[(row + g + 8) * AS_STRIDE + kk + tg    ]);
                afr[mt][2] = f2tf32(As[(row + g    ) * AS_STRIDE + kk + tg + 4]);
                afr[mt][3] = f2tf32(As[(row + g + 8) * AS_STRIDE + kk + tg + 4]);
            }
            #pragma unroll
            for (int nt = 0; nt < 4; nt++) {
                int ncol = wn * 32 + nt * 8;
                unsigned b0 = f2tf32(Bs[(kk + tg    ) * BS_STRIDE + ncol + g]);
                unsigned b1 = f2tf32(Bs[(kk + tg + 4) * BS_STRIDE + ncol + g]);
                #pragma unroll
                for (int mt = 0; mt < 2; mt++)
                    mma_tf32(acc[mt][nt], afr[mt], b0, b1);
            }
        }
        __syncthreads();
    }

    // store: c0,c1 -> (row, 2tg..2tg+1); c2,c3 -> (row+8, ...)
    #pragma unroll
    for (int mt = 0; mt < 2; mt++) {
        int r0 = m0 + wm * 32 + mt * 16 + g;
        #pragma unroll
        for (int nt = 0; nt < 4; nt++) {
            int col = n0g + wn * 32 + nt * 8 + tg * 2;
            float* Cp = C0;
            int c = col;
            if (col >= H) { Cp = C1; c = col - H; }
            if (r0 < M)
                *reinterpret_cast<float2*>(Cp + (size_t)r0 * H + c) =
                    make_float2(acc[mt][nt][0], acc[mt][nt][1]);
            if (r0 + 8 < M)
                *reinterpret_cast<float2*>(Cp + (size_t)(r0 + 8) * H + c) =
                    make_float2(acc[mt][nt][2], acc[mt][nt][3]);
        }
    }
}

// ---------------- vector load helper ----------------
template <int V>
__device__ __forceinline__ void loadv(float* d, const float* __restrict__ p) {
    if constexpr (V == 8) {
        float4 a = *reinterpret_cast<const float4*>(p);
        float4 b = *reinterpret_cast<const float4*>(p + 4);
        d[0] = a.x; d[1] = a.y; d[2] = a.z; d[3] = a.w;
        d[4] = b.x; d[5] = b.y; d[6] = b.z; d[7] = b.w;
    } else if constexpr (V == 2) {
        float2 a = *reinterpret_cast<const float2*>(p);
        d[0] = a.x; d[1] = a.y;
    } else {
        #pragma unroll
        for (int j = 0; j < V; j++) d[j] = p[j];
    }
}

// ---------------- GATv2 node aggregation: warp per node, online softmax ----------------
// HC = H*C total width; VPT = HC/32 per lane; REDW = 32/H lanes per head.
// R3-style loop: branchy (rarely-taken) rescale, no prefetch.
// STATS: fuse per-channel sum/sumsq accumulation (layer-2 InstanceNorm).
template <int HC, int VPT, int REDW, bool ELU_ACT, bool STATS>
__global__ __launch_bounds__(256) void k_node_agg(
    const float* __restrict__ xl, const float* __restrict__ xr,
    const float* __restrict__ att, const float* __restrict__ bias,
    float* __restrict__ outp, int N)
{
    __shared__ float sh_sum[STATS ? 64 : 1];
    __shared__ float sh_sq [STATS ? 64 : 1];
    int tid = threadIdx.x;
    if (STATS) {
        if (tid < 64) { sh_sum[tid] = 0.f; sh_sq[tid] = 0.f; }
        __syncthreads();
    }

    int warp = (blockIdx.x * blockDim.x + tid) >> 5;
    int lane = tid & 31;
    bool active = warp < N;
    int c0 = lane * VPT;

    if (active) {
        int n = warp;
        float xrv[VPT], attv[VPT], acc[VPT];
        loadv<VPT>(xrv, xr + (size_t)n * HC + c0);
        loadv<VPT>(attv, att + c0);
        #pragma unroll
        for (int j = 0; j < VPT; j++) acc[j] = 0.f;

        float m = __int_as_float(0xff800000);   // -inf
        float denom = 0.f;

        int s = g_off[n], e = g_off[n + 1];
        for (int i = s; i < e; i++) {
            int src = g_csrc[i];
            float xlv[VPT];
            loadv<VPT>(xlv, xl + (size_t)src * HC + c0);

            float sc = 0.f;
            #pragma unroll
            for (int j = 0; j < VPT; j++) {
                float t = xlv[j] + xrv[j];
                t = (t > 0.f) ? t : 0.2f * t;   // leaky_relu slope 0.2
                sc = fmaf(t, attv[j], sc);
            }
            #pragma unroll
            for (int w = 1; w < REDW; w <<= 1)
                sc += __shfl_xor_sync(0xffffffffu, sc, w);

            if (sc > m) {                        // online softmax rescale
                float r = __expf(m - sc);        // exp(-inf)=0 on first edge
                denom *= r;
                #pragma unroll
                for (int j = 0; j < VPT; j++) acc[j] *= r;
                m = sc;
            }
            float ex = __expf(sc - m);
            denom += ex;
            #pragma unroll
            for (int j = 0; j < VPT; j++) acc[j] = fmaf(ex, xlv[j], acc[j]);
        }

        float inv = 1.f / (denom + 1e-16f);
        #pragma unroll
        for (int j = 0; j < VPT; j++) {
            float v = acc[j] * inv + bias[c0 + j];
            if (ELU_ACT) v = (v > 0.f) ? v : (__expf(v) - 1.f);  // ELU alpha=1
            outp[(size_t)n * HC + c0 + j] = v;
            if (STATS) {
                atomicAdd(&sh_sum[c0 + j], v);
                atomicAdd(&sh_sq [c0 + j], v * v);
            }
        }
    }

    if (STATS) {
        __syncthreads();
        if (tid < 64) {
            atomicAdd(&g_sum[tid],   sh_sum[tid]);
            atomicAdd(&g_sumsq[tid], sh_sq[tid]);
        }
    }
}

// ---------------- InstanceNorm + log_softmax epilogue (warp per node) ----------------
__global__ __launch_bounds__(256) void k_final(
    const float* __restrict__ h,
    const float* __restrict__ gamma, const float* __restrict__ beta,
    float* __restrict__ out, int N)
{
    int gw = (blockIdx.x * blockDim.x + threadIdx.x) >> 5;
    int lane = threadIdx.x & 31;
    if (gw >= N) return;
    int c0 = lane * 2;

    float2 x = *reinterpret_cast<const float2*>(h + (size_t)gw * 64 + c0);
    float invN = 1.f / (float)N;

    float mean0 = g_sum[c0] * invN;
    float var0  = g_sumsq[c0] * invN - mean0 * mean0;
    float y0 = (x.x - mean0) * rsqrtf(var0 + 1e-5f) * gamma[c0] + beta[c0];

    float mean1 = g_sum[c0 + 1] * invN;
    float var1  = g_sumsq[c0 + 1] * invN - mean1 * mean1;
    float y1 = (x.y - mean1) * rsqrtf(var1 + 1e-5f) * gamma[c0 + 1] + beta[c0 + 1];

    float2 yv = make_float2(y0, y1);
    *reinterpret_cast<float2*>(out + (size_t)gw * 64 + c0) = yv;

    float mx = fmaxf(y0, y1);
    #pragma unroll
    for (int w = 1; w < 32; w <<= 1) mx = fmaxf(mx, __shfl_xor_sync(0xffffffffu, mx, w));
    float se = __expf(y0 - mx) + __expf(y1 - mx);
    #pragma unroll
    for (int w = 1; w < 32; w <<= 1) se += __shfl_xor_sync(0xffffffffu, se, w);
    float ls = __logf(se) + mx;          // log-sum-exp

    float2 lv = make_float2(y0 - ls, y1 - ls);
    *reinterpret_cast<float2*>(out + (size_t)N * 64 + (size_t)gw * 64 + c0) = lv;
}

// ---------------- host launcher ----------------
extern "C" void kernel_launch(void* const* d_in, const int* in_sizes, int n_in,
                              void* d_out, int out_size)
{
    const float* x     = (const float*)d_in[0];
    const float* Wl1   = (const float*)d_in[1];
    const float* Wr1   = (const float*)d_in[2];
    const float* att1  = (const float*)d_in[3];
    const float* b1    = (const float*)d_in[4];
    const float* Wl2   = (const float*)d_in[5];
    const float* Wr2   = (const float*)d_in[6];
    const float* att2  = (const float*)d_in[7];
    const float* b2    = (const float*)d_in[8];
    const float* gamma = (const float*)d_in[9];
    const float* beta  = (const float*)d_in[10];
    const int*   ei    = (const int*)  d_in[11];   // [2, E] int32

    int N = in_sizes[0] / 128;
    int E = in_sizes[11] / 2;

    void *p;
    cudaGetSymbolAddress(&p, g_xl1); float* xl1 = (float*)p;
    cudaGetSymbolAddress(&p, g_xr1); float* xr1 = (float*)p;
    cudaGetSymbolAddress(&p, g_h1 ); float* h1  = (float*)p;
    cudaGetSymbolAddress(&p, g_xl2); float* xl2 = (float*)p;
    cudaGetSymbolAddress(&p, g_xr2); float* xr2 = (float*)p;
    cudaGetSymbolAddress(&p, g_h2 ); float* h2  = (float*)p;

    static bool attr_set = false;
    if (!attr_set) {
        cudaFuncSetAttribute(k_mma, cudaFuncAttributeMaxDynamicSharedMemorySize,
                             SMEM_MMA_BYTES);
        attr_set = true;
    }

    // CSR build (self-loops folded into init/scan)
    k_init<<<(N + 255) / 256, 256>>>(N);
    k_count<<<(E + 255) / 256, 256>>>(ei, E);
    k_scan2<<<1, 1024>>>(N);
    k_fill<<<(E + 255) / 256, 256>>>(ei, E);

    // Layer 1: [xl1 | xr1] = x @ [Wl1 | Wr1]  (M=N, K=128, H=256, 2H=512)
    {
        dim3 grid((N + 63) / 64, 4);
        k_mma<<<grid, 256, SMEM_MMA_BYTES>>>(x, Wl1, Wr1, xl1, xr1, N, 128, 256);
    }
    // GATv2 layer 1 (H=8, C=32) + bias + ELU
    k_node_agg<256, 8, 4, true, false><<<(N * 32 + 255) / 256, 256>>>(xl1, xr1, att1, b1, h1, N);

    // Layer 2: [xl2 | xr2] = h1 @ [Wl2 | Wr2]  (M=N, K=256, H=64, 2H=128)
    {
        dim3 grid((N + 63) / 64, 1);
        k_mma<<<grid, 256, SMEM_MMA_BYTES>>>(h1, Wl2, Wr2, xl2, xr2, N, 256, 64);
    }
    // GATv2 layer 2 (H=1, C=64) + bias + fused InstanceNorm stats
    k_node_agg<64, 2, 32, false, true><<<(N * 32 + 255) / 256, 256>>>(xl2, xr2, att2, b2, h2, N);

    // InstanceNorm normalize + log_softmax
    k_final<<<(N * 32 + 255) / 256, 256>>>(h2, gamma, beta, (float*)d_out, N);
}

// round 7
// speedup vs baseline: 1.0612x; 1.0510x over previous
#include <cuda_runtime.h>
#include <cstdint>
#include <cstdio>

// Problem-size capacities (from reference setup: N=20000, E=320000)
#define NMAXN 20000
#define EMAXE 320000
#define ETOT  (NMAXN + EMAXE)

// ---------------- static device scratch (no allocations allowed) ----------------
__device__ __align__(16) float g_xl1[NMAXN * 256];
__device__ __align__(16) float g_xr1[NMAXN * 256];
__device__ __align__(16) float g_h1 [NMAXN * 256];
__device__ __align__(16) float g_xl2[NMAXN * 64];
__device__ __align__(16) float g_xr2[NMAXN * 64];
__device__ __align__(16) float g_h2 [NMAXN * 64];
__device__ int   g_deg[NMAXN + 1];
__device__ int   g_off[NMAXN + 1];
__device__ int   g_cur[NMAXN];
__device__ int   g_csrc[ETOT];
__device__ float g_sum[64];
__device__ float g_sumsq[64];

// ---------------- init: deg=1 accounts for the self-loop ----------------
__global__ void k_init(int N) {
    int i = blockIdx.x * blockDim.x + threadIdx.x;
    if (i < N) g_deg[i] = 1;
    if (i < 64) { g_sum[i] = 0.f; g_sumsq[i] = 0.f; }
}

// ---------------- CSR build (by dst), E edges only ----------------
__global__ void k_count(const int* __restrict__ ei, int E) {
    int i = blockIdx.x * blockDim.x + threadIdx.x;
    if (i >= E) return;
    atomicAdd(&g_deg[__ldg(ei + E + i)], 1);
}

// single-block chunked scan; writes the self-loop into slot 0 of each
// node's segment and initializes g_cur = off + 1.
#define SCAN_PER ((NMAXN + 1023) / 1024)
__global__ __launch_bounds__(1024) void k_scan2(int N) {
    __shared__ int sh[1024];
    int tid = threadIdx.x;
    int base = tid * SCAN_PER;
    int vals[SCAN_PER];
    int s = 0;
    #pragma unroll
    for (int i = 0; i < SCAN_PER; i++) {
        int idx = base + i;
        int v = (idx < N) ? g_deg[idx] : 0;
        vals[i] = s;          // exclusive within chunk
        s += v;
    }
    sh[tid] = s;
    __syncthreads();
    #pragma unroll
    for (int o = 1; o < 1024; o <<= 1) {
        int t = (tid >= o) ? sh[tid - o] : 0;
        __syncthreads();
        sh[tid] += t;
        __syncthreads();
    }
    int block_excl = sh[tid] - s;
    #pragma unroll
    for (int i = 0; i < SCAN_PER; i++) {
        int idx = base + i;
        if (idx < N) {
            int o = block_excl + vals[i];
            g_off[idx] = o;
            g_csrc[o] = idx;      // self-loop occupies slot 0
            g_cur[idx] = o + 1;
        }
    }
    if (tid == 1023) g_off[N] = sh[1023];
}

__global__ void k_fill(const int* __restrict__ ei, int E) {
    int i = blockIdx.x * blockDim.x + threadIdx.x;
    if (i >= E) return;
    int src = __ldg(ei + i);
    int dst = __ldg(ei + E + i);
    int pos = atomicAdd(&g_cur[dst], 1);
    g_csrc[pos] = src;
}

// ---------------- tf32 tensor-core GEMM, cp.async double-buffered ----------------
// C_concat[M, 2H] = A[M, K] @ concat(B0, B1)[K, 2H], written to C0/C1 halves.
// Block: 256 threads = 8 warps (2 m x 4 n), tile 64(M) x 128(N) x 32(K).
__device__ __forceinline__ unsigned f2tf32(float f) {
    unsigned u;
    asm("cvt.rna.tf32.f32 %0, %1;" : "=r"(u) : "f"(f));
    return u;
}

__device__ __forceinline__ void mma_tf32(float* d, const unsigned* a, unsigned b0, unsigned b1) {
    asm volatile(
        "mma.sync.aligned.m16n8k8.row.col.f32.tf32.tf32.f32 "
        "{%0,%1,%2,%3}, {%4,%5,%6,%7}, {%8,%9}, {%0,%1,%2,%3};"
        : "+f"(d[0]), "+f"(d[1]), "+f"(d[2]), "+f"(d[3])
        : "r"(a[0]), "r"(a[1]), "r"(a[2]), "r"(a[3]), "r"(b0), "r"(b1));
}

__device__ __forceinline__ void cp_async16(uint32_t saddr, const void* g, int srcbytes) {
    asm volatile("cp.async.cg.shared.global [%0], [%1], 16, %2;"
                 :: "r"(saddr), "l"(g), "r"(srcbytes));
}

#define AS_STRIDE 36
#define BS_STRIDE 136
#define AS_STAGE  (64 * AS_STRIDE)      // floats per A stage
#define BS_STAGE  (32 * BS_STRIDE)      // floats per B stage
#define SMEM_MMA_BYTES ((2 * AS_STAGE + 2 * BS_STAGE) * 4)

__global__ __launch_bounds__(256) void k_mma(
    const float* __restrict__ A,
    const float* __restrict__ B0, const float* __restrict__ B1,
    float* __restrict__ C0, float* __restrict__ C1,
    int M, int K, int H)
{
    extern __shared__ float smem[];
    float* sAs = smem;                       // [2][64][36]
    float* sBs = smem + 2 * AS_STAGE;        // [2][32][136]

    int tid = threadIdx.x;
    int lane = tid & 31, warp = tid >> 5;
    int wm = warp & 1, wn = warp >> 1;       // 2 x 4 warp grid
    int m0 = blockIdx.x * 64;
    int n0g = blockIdx.y * 128;              // col in concatenated [0, 2H) space
    int g = lane >> 2, tg = lane & 3;

    float acc[2][4][4];
    #pragma unroll
    for (int mt = 0; mt < 2; mt++)
        #pragma unroll
        for (int nt = 0; nt < 4; nt++)
            #pragma unroll
            for (int i = 0; i < 4; i++) acc[mt][nt][i] = 0.f;

    int ar = tid >> 2;          // 0..63
    int ac = (tid & 3) * 8;     // 0,8,16,24
    int br = tid >> 3;          // 0..31
    int bc = (tid & 7) * 16;    // 0..112

    // per-thread source pointers / predicates (row clamped, zero-filled when OOB)
    int arow = m0 + ar;
    int apred = (arow < M) ? 16 : 0;
    if (arow >= M) arow = M - 1;
    const float* abase = A + (size_t)arow * K + ac;

    const float* bsrc[4];
    #pragma unroll
    for (int i = 0; i < 4; i++) {
        int col = n0g + bc + i * 4;
        bsrc[i] = (col < H) ? (B0 + (size_t)br * H + col)
                            : (B1 + (size_t)br * H + (col - H));
    }

    uint32_t sA0 = (uint32_t)__cvta_generic_to_shared(sAs);
    uint32_t sB0 = (uint32_t)__cvta_generic_to_shared(sBs);

    int nIter = K >> 5;

    // ---- stage loader ----
    auto load_stage = [&](int k0, int st) {
        uint32_t sa = sA0 + (st * AS_STAGE + ar * AS_STRIDE + ac) * 4;
        const float* ap = abase + k0;
        cp_async16(sa,      ap,     apred);
        cp_async16(sa + 16, ap + 4, apred);
        uint32_t sb = sB0 + (st * BS_STAGE + br * BS_STRIDE + bc) * 4;
        size_t koff = (size_t)k0 * H;
        #pragma unroll
        for (int i = 0; i < 4; i++)
            cp_async16(sb + i * 16, bsrc[i] + koff, 16);
    };

    load_stage(0, 0);
    asm volatile("cp.async.commit_group;" ::: "memory");

    for (int it = 0; it < nIter; it++) {
        int st = it & 1;
        asm volatile("cp.async.wait_group 0;" ::: "memory");
        __syncthreads();
        if (it + 1 < nIter) {
            load_stage((it + 1) << 5, st ^ 1);
            asm volatile("cp.async.commit_group;" ::: "memory");
        }

        const float* As = sAs + st * AS_STAGE;
        const float* Bs = sBs + st * BS_STAGE;

        #pragma unroll
        for (int kk = 0; kk < 32; kk += 8) {
            unsigned afr[2][4];
            #pragma unroll
            for (int mt = 0; mt < 2; mt++) {
                int row = wm * 32 + mt * 16;
                afr[mt][0] = f2tf32(As[(row + g    ) * AS_STRIDE + kk + tg    ]);
                afr[mt][1] = f2tf32(As[(row + g + 8) * AS_STRIDE + kk + tg    ]);
                afr[mt][2] = f2tf32(As[(row + g    ) * AS_STRIDE + kk + tg + 4]);
                afr[mt][3] = f2tf32(As[(row + g + 8) * AS_STRIDE + kk + tg + 4]);
            }
            #pragma unroll
            for (int nt = 0; nt < 4; nt++) {
                int ncol = wn * 32 + nt * 8;
                unsigned b0 = f2tf32(Bs[(kk + tg    ) * BS_STRIDE + ncol + g]);
                unsigned b1 = f2tf32(Bs[(kk + tg + 4) * BS_STRIDE + ncol + g]);
                #pragma unroll
                for (int mt = 0; mt < 2; mt++)
                    mma_tf32(acc[mt][nt], afr[mt], b0, b1);
            }
        }
        __syncthreads();
    }

    // store: c0,c1 -> (row, 2tg..2tg+1); c2,c3 -> (row+8, ...)
    #pragma unroll
    for (int mt = 0; mt < 2; mt++) {
        int r0 = m0 + wm * 32 + mt * 16 + g;
        #pragma unroll
        for (int nt = 0; nt < 4; nt++) {
            int col = n0g + wn * 32 + nt * 8 + tg * 2;
            float* Cp = C0;
            int c = col;
            if (col >= H) { Cp = C1; c = col - H; }
            if (r0 < M)
                *reinterpret_cast<float2*>(Cp + (size_t)r0 * H + c) =
                    make_float2(acc[mt][nt][0], acc[mt][nt][1]);
            if (r0 + 8 < M)
                *reinterpret_cast<float2*>(Cp + (size_t)(r0 + 8) * H + c) =
                    make_float2(acc[mt][nt][2], acc[mt][nt][3]);
        }
    }
}

// ---------------- vector load helper ----------------
template <int V>
__device__ __forceinline__ void loadv(float* d, const float* __restrict__ p) {
    if constexpr (V == 8) {
        float4 a = *reinterpret_cast<const float4*>(p);
        float4 b = *reinterpret_cast<const float4*>(p + 4);
        d[0] = a.x; d[1] = a.y; d[2] = a.z; d[3] = a.w;
        d[4] = b.x; d[5] = b.y; d[6] = b.z; d[7] = b.w;
    } else if constexpr (V == 2) {
        float2 a = *reinterpret_cast<const float2*>(p);
        d[0] = a.x; d[1] = a.y;
    } else {
        #pragma unroll
        for (int j = 0; j < V; j++) d[j] = p[j];
    }
}

// ---------------- GATv2 node aggregation: warp per node, online softmax ----------------
// HC = H*C total width; VPT = HC/32 per lane; REDW = 32/H lanes per head.
// 2-edge unrolled loop: both rows in flight (2x MLP), one exact fused pair update.
// STATS: fuse per-channel sum/sumsq accumulation (layer-2 InstanceNorm).
template <int HC, int VPT, int REDW, bool ELU_ACT, bool STATS>
__global__ __launch_bounds__(256) void k_node_agg(
    const float* __restrict__ xl, const float* __restrict__ xr,
    const float* __restrict__ att, const float* __restrict__ bias,
    float* __restrict__ outp, int N)
{
    __shared__ float sh_sum[STATS ? 64 : 1];
    __shared__ float sh_sq [STATS ? 64 : 1];
    int tid = threadIdx.x;
    if (STATS) {
        if (tid < 64) { sh_sum[tid] = 0.f; sh_sq[tid] = 0.f; }
        __syncthreads();
    }

    int warp = (blockIdx.x * blockDim.x + tid) >> 5;
    int lane = tid & 31;
    bool active = warp < N;
    int c0 = lane * VPT;

    if (active) {
        int n = warp;
        float xrv[VPT], attv[VPT], acc[VPT];
        loadv<VPT>(xrv, xr + (size_t)n * HC + c0);
        loadv<VPT>(attv, att + c0);
        #pragma unroll
        for (int j = 0; j < VPT; j++) acc[j] = 0.f;

        float m = __int_as_float(0xff800000);   // -inf
        float denom = 0.f;

        int s = g_off[n], e = g_off[n + 1];
        int i = s;
        for (; i + 2 <= e; i += 2) {
            int s0 = g_csrc[i];
            int s1 = g_csrc[i + 1];
            float xlv0[VPT], xlv1[VPT];
            loadv<VPT>(xlv0, xl + (size_t)s0 * HC + c0);
            loadv<VPT>(xlv1, xl + (size_t)s1 * HC + c0);

            float sc0 = 0.f, sc1 = 0.f;
            #pragma unroll
            for (int j = 0; j < VPT; j++) {
                float t0 = xlv0[j] + xrv[j];
                float t1 = xlv1[j] + xrv[j];
                t0 = (t0 > 0.f) ? t0 : 0.2f * t0;
                t1 = (t1 > 0.f) ? t1 : 0.2f * t1;
                sc0 = fmaf(t0, attv[j], sc0);
                sc1 = fmaf(t1, attv[j], sc1);
            }
            #pragma unroll
            for (int w = 1; w < REDW; w <<= 1) {
                sc0 += __shfl_xor_sync(0xffffffffu, sc0, w);
                sc1 += __shfl_xor_sync(0xffffffffu, sc1, w);
            }

            // exact fused pair update
            float newm = fmaxf(m, fmaxf(sc0, sc1));
            float r  = __expf(m - newm);       // 0 on first iter (m = -inf)
            float e0 = __expf(sc0 - newm);
            float e1 = __expf(sc1 - newm);
            denom = fmaf(denom, r, e0 + e1);
            #pragma unroll
            for (int j = 0; j < VPT; j++)
                acc[j] = fmaf(acc[j], r, fmaf(e0, xlv0[j], e1 * xlv1[j]));
            m = newm;
        }
        if (i < e) {                            // tail edge (branchy update)
            int src = g_csrc[i];
            float xlv[VPT];
            loadv<VPT>(xlv, xl + (size_t)src * HC + c0);
            float sc = 0.f;
            #pragma unroll
            for (int j = 0; j < VPT; j++) {
                float t = xlv[j] + xrv[j];
                t = (t > 0.f) ? t : 0.2f * t;
                sc = fmaf(t, attv[j], sc);
            }
            #pragma unroll
            for (int w = 1; w < REDW; w <<= 1)
                sc += __shfl_xor_sync(0xffffffffu, sc, w);
            if (sc > m) {
                float r = __expf(m - sc);
                denom *= r;
                #pragma unroll
                for (int j = 0; j < VPT; j++) acc[j] *= r;
                m = sc;
            }
            float ex = __expf(sc - m);
            denom += ex;
            #pragma unroll
            for (int j = 0; j < VPT; j++) acc[j] = fmaf(ex, xlv[j], acc[j]);
        }

        float inv = 1.f / (denom + 1e-16f);
        #pragma unroll
        for (int j = 0; j < VPT; j++) {
            float v = acc[j] * inv + bias[c0 + j];
            if (ELU_ACT) v = (v > 0.f) ? v : (__expf(v) - 1.f);  // ELU alpha=1
            outp[(size_t)n * HC + c0 + j] = v;
            if (STATS) {
                atomicAdd(&sh_sum[c0 + j], v);
                atomicAdd(&sh_sq [c0 + j], v * v);
            }
        }
    }

    if (STATS) {
        __syncthreads();
        if (tid < 64) {
            atomicAdd(&g_sum[tid],   sh_sum[tid]);
            atomicAdd(&g_sumsq[tid], sh_sq[tid]);
        }
    }
}

// ---------------- InstanceNorm + log_softmax epilogue (warp per node) ----------------
__global__ __launch_bounds__(256) void k_final(
    const float* __restrict__ h,
    const float* __restrict__ gamma, const float* __restrict__ beta,
    float* __restrict__ out, int N)
{
    int gw = (blockIdx.x * blockDim.x + threadIdx.x) >> 5;
    int lane = threadIdx.x & 31;
    if (gw >= N) return;
    int c0 = lane * 2;

    float2 x = *reinterpret_cast<const float2*>(h + (size_t)gw * 64 + c0);
    float invN = 1.f / (float)N;

    float mean0 = g_sum[c0] * invN;
    float var0  = g_sumsq[c0] * invN - mean0 * mean0;
    float y0 = (x.x - mean0) * rsqrtf(var0 + 1e-5f) * gamma[c0] + beta[c0];

    float mean1 = g_sum[c0 + 1] * invN;
    float var1  = g_sumsq[c0 + 1] * invN - mean1 * mean1;
    float y1 = (x.y - mean1) * rsqrtf(var1 + 1e-5f) * gamma[c0 + 1] + beta[c0 + 1];

    float2 yv = make_float2(y0, y1);
    *reinterpret_cast<float2*>(out + (size_t)gw * 64 + c0) = yv;

    float mx = fmaxf(y0, y1);
    #pragma unroll
    for (int w = 1; w < 32; w <<= 1) mx = fmaxf(mx, __shfl_xor_sync(0xffffffffu, mx, w));
    float se = __expf(y0 - mx) + __expf(y1 - mx);
    #pragma unroll
    for (int w = 1; w < 32; w <<= 1) se += __shfl_xor_sync(0xffffffffu, se, w);
    float ls = __logf(se) + mx;          // log-sum-exp

    float2 lv = make_float2(y0 - ls, y1 - ls);
    *reinterpret_cast<float2*>(out + (size_t)N * 64 + (size_t)gw * 64 + c0) = lv;
}

// ---------------- host launcher ----------------
extern "C" void kernel_launch(void* const* d_in, const int* in_sizes, int n_in,
                              void* d_out, int out_size)
{
    const float* x     = (const float*)d_in[0];
    const float* Wl1   = (const float*)d_in[1];
    const float* Wr1   = (const float*)d_in[2];
    const float* att1  = (const float*)d_in[3];
    const float* b1    = (const float*)d_in[4];
    const float* Wl2   = (const float*)d_in[5];
    const float* Wr2   = (const float*)d_in[6];
    const float* att2  = (const float*)d_in[7];
    const float* b2    = (const float*)d_in[8];
    const float* gamma = (const float*)d_in[9];
    const float* beta  = (const float*)d_in[10];
    const int*   ei    = (const int*)  d_in[11];   // [2, E] int32

    int N = in_sizes[0] / 128;
    int E = in_sizes[11] / 2;

    void *p;
    cudaGetSymbolAddress(&p, g_xl1); float* xl1 = (float*)p;
    cudaGetSymbolAddress(&p, g_xr1); float* xr1 = (float*)p;
    cudaGetSymbolAddress(&p, g_h1 ); float* h1  = (float*)p;
    cudaGetSymbolAddress(&p, g_xl2); float* xl2 = (float*)p;
    cudaGetSymbolAddress(&p, g_xr2); float* xr2 = (float*)p;
    cudaGetSymbolAddress(&p, g_h2 ); float* h2  = (float*)p;

    static bool attr_set = false;
    if (!attr_set) {
        cudaFuncSetAttribute(k_mma, cudaFuncAttributeMaxDynamicSharedMemorySize,
                             SMEM_MMA_BYTES);
        attr_set = true;
    }

    // CSR build (self-loops folded into init/scan)
    k_init<<<(N + 255) / 256, 256>>>(N);
    k_count<<<(E + 255) / 256, 256>>>(ei, E);
    k_scan2<<<1, 1024>>>(N);
    k_fill<<<(E + 255) / 256, 256>>>(ei, E);

    // Layer 1: [xl1 | xr1] = x @ [Wl1 | Wr1]  (M=N, K=128, H=256, 2H=512)
    {
        dim3 grid((N + 63) / 64, 4);
        k_mma<<<grid, 256, SMEM_MMA_BYTES>>>(x, Wl1, Wr1, xl1, xr1, N, 128, 256);
    }
    // GATv2 layer 1 (H=8, C=32) + bias + ELU
    k_node_agg<256, 8, 4, true, false><<<(N * 32 + 255) / 256, 256>>>(xl1, xr1, att1, b1, h1, N);

    // Layer 2: [xl2 | xr2] = h1 @ [Wl2 | Wr2]  (M=N, K=256, H=64, 2H=128)
    {
        dim3 grid((N + 63) / 64, 1);
        k_mma<<<grid, 256, SMEM_MMA_BYTES>>>(h1, Wl2, Wr2, xl2, xr2, N, 256, 64);
    }
    // GATv2 layer 2 (H=1, C=64) + bias + fused InstanceNorm stats
    k_node_agg<64, 2, 32, false, true><<<(N * 32 + 255) / 256, 256>>>(xl2, xr2, att2, b2, h2, N);

    // InstanceNorm normalize + log_softmax
    k_final<<<(N * 32 + 255) / 256, 256>>>(h2, gamma, beta, (float*)d_out, N);
}